// round 13
// baseline (speedup 1.0000x reference)
#include <cuda_runtime.h>
#include <cuda_bf16.h>

// Problem dims
#define BATCH  64
#define SDIM   4096
#define DDIM   256
#define UROWS  128                          // rows per work unit
#define UPB    (SDIM / UROWS)               // 32 units per batch
#define NUNITS (BATCH * UPB)                // 2048 units
#define GRID   592                          // 148 SMs x occ 4 — all resident

// Persistent state (no allocation allowed -> device globals, zero-init)
__device__ float    g_acc[BATCH * DDIM];
__device__ float    g_sum[BATCH];
__device__ unsigned g_unit;                 // work-stealing cursor
__device__ unsigned g_done;                 // completion counter

__device__ __forceinline__ float warp_sum(float v) {
    #pragma unroll
    for (int o = 16; o; o >>= 1) v += __shfl_xor_sync(0xffffffffu, v, o);
    return v;
}

// exp(tanh(x)) via tanh(x) = 1 - 2/(e^{2x}+1); saturates correctly at +-1.
// Validated at rel_err ~1.0e-6 across R9-R12.
__device__ __forceinline__ float exp_tanh(float x) {
    const float t  = __expf(2.f * x);
    const float th = 1.f - __fdividef(2.f, t + 1.f);
    return __expf(th);
}

__device__ __forceinline__ float dot8(const float4& m0, const float4& m1,
                                      const float4& w0, const float4& w1) {
    return m0.x * w0.x + m0.y * w0.y + m0.z * w0.z + m0.w * w0.w
         + m1.x * w1.x + m1.y * w1.y + m1.z * w1.z + m1.w * w1.w;
}

// ---------------------------------------------------------------------------
// Persistent work-stealing version of the single-pass kernel.
//   gi = tanh(m·Wm + c_b) in [-1,1] => exp never overflows => softmax needs
//   no running max; accumulate exp(gi)*m and exp(gi) in one sweep.
// 2048 units of 128 rows pulled from a global cursor: early-finishing SMs
// steal the stragglers' work, flattening the end-of-kernel tail that capped
// R4-R12 at ~75% DRAM. Units are batch-ordered so register accumulators
// flush (global atomicAdd) only on rare batch boundaries. The last CTA to
// finish writes the output and re-arms all global state for graph replay.
// ---------------------------------------------------------------------------
__global__ __launch_bounds__(256, 4)
void att_persist(const float* __restrict__ memory,
                 const float* __restrict__ aspect,
                 const float* __restrict__ W,
                 const float* __restrict__ bias,
                 float* __restrict__ out)
{
    __shared__ float    s_cb[BATCH];
    __shared__ unsigned s_u;

    const int tid  = threadIdx.x;
    const int lane = tid & 31;
    const int warp = tid >> 5;

    // ---- all 64 cb values, computed once per CTA (tiny, L2-resident) ----
    {
        const float bias0 = bias[0];
        for (int b = warp; b < BATCH; b += 8) {
            float v = 0.f;
            #pragma unroll
            for (int k = 0; k < 8; k++)
                v += aspect[b * DDIM + lane + 32 * k] * W[DDIM + lane + 32 * k];
            v = warp_sum(v);
            if (lane == 0) s_cb[b] = v + bias0;
        }
    }
    __syncthreads();

    // ---- Wm slice in registers: lane covers d = 4*lane.. and 128+4*lane.. ----
    const float4 wm0 = *reinterpret_cast<const float4*>(W + 4 * lane);
    const float4 wm1 = *reinterpret_cast<const float4*>(W + 128 + 4 * lane);

    float4 a0 = make_float4(0.f, 0.f, 0.f, 0.f);
    float4 a1 = make_float4(0.f, 0.f, 0.f, 0.f);
    float  sw = 0.f;
    int    cur_b = -1;
    float  cb = 0.f;

    const float4* mem4 = reinterpret_cast<const float4*>(memory);
    const long rstep = 8 * 64;              // 8 rows of 64 float4

    // flush register accumulators into g_acc[fb] (rare: ~2x per CTA)
    auto flush = [&](int fb) {
        if (fb < 0) return;
        float* dst = &g_acc[fb * DDIM];
        atomicAdd(&dst[4 * lane + 0], a0.x);
        atomicAdd(&dst[4 * lane + 1], a0.y);
        atomicAdd(&dst[4 * lane + 2], a0.z);
        atomicAdd(&dst[4 * lane + 3], a0.w);
        atomicAdd(&dst[128 + 4 * lane + 0], a1.x);
        atomicAdd(&dst[128 + 4 * lane + 1], a1.y);
        atomicAdd(&dst[128 + 4 * lane + 2], a1.z);
        atomicAdd(&dst[128 + 4 * lane + 3], a1.w);
        if (lane == 0) atomicAdd(&g_sum[fb], sw);
        a0 = make_float4(0.f, 0.f, 0.f, 0.f);
        a1 = make_float4(0.f, 0.f, 0.f, 0.f);
        sw = 0.f;
    };

    for (;;) {
        __syncthreads();                    // protect s_u reuse across grabs
        if (tid == 0) s_u = atomicAdd(&g_unit, 1u);
        __syncthreads();
        const unsigned u = s_u;
        if (u >= NUNITS) break;

        const int b = (int)(u >> 5);        // / UPB
        if (b != cur_b) { flush(cur_b); cur_b = b; cb = s_cb[b]; }

        // unit rows: [ (u%UPB)*UROWS , +UROWS ) of batch b; warp takes warp+8i
        const float4* p = mem4
            + ((long)b * SDIM + (long)(u & (UPB - 1)) * UROWS + warp) * 64;

        // ---- R12 pair-pipeline over 16 rows (8 iters, 2-row prefetch) ----
        float4 c00 = __ldcs(p + lane),         c01 = __ldcs(p + 32 + lane);
        float4 c10 = __ldcs(p + rstep + lane), c11 = __ldcs(p + rstep + 32 + lane);

        #pragma unroll 2
        for (int i = 0; i < 16; i += 2) {
            float4 n00, n01, n10, n11;
            if (i + 2 < 16) {
                const float4* q = p + (long)(i + 2) * rstep;
                n00 = __ldcs(q + lane);          n01 = __ldcs(q + 32 + lane);
                n10 = __ldcs(q + rstep + lane);  n11 = __ldcs(q + rstep + 32 + lane);
            }

            float d0 = warp_sum(dot8(c00, c01, wm0, wm1));
            float d1 = warp_sum(dot8(c10, c11, wm0, wm1));
            const float w0 = exp_tanh(d0 + cb);
            const float w1 = exp_tanh(d1 + cb);

            a0.x += w0 * c00.x + w1 * c10.x;  a0.y += w0 * c00.y + w1 * c10.y;
            a0.z += w0 * c00.z + w1 * c10.z;  a0.w += w0 * c00.w + w1 * c10.w;
            a1.x += w0 * c01.x + w1 * c11.x;  a1.y += w0 * c01.y + w1 * c11.y;
            a1.z += w0 * c01.z + w1 * c11.z;  a1.w += w0 * c01.w + w1 * c11.w;
            sw   += w0 + w1;                  // uniform across lanes post-butterfly

            c00 = n00; c01 = n01; c10 = n10; c11 = n11;
        }
    }

    flush(cur_b);

    // ---- completion: the last CTA to arrive finalizes + re-arms ----
    __threadfence();                        // publish my flushes
    __syncthreads();
    if (tid == 0) s_u = atomicAdd(&g_done, 1u);
    __syncthreads();
    if (s_u == GRID - 1) {
        __threadfence();                    // acquire everyone's flushes
        #pragma unroll 4
        for (int b = 0; b < BATCH; b++) {
            const float inv = __fdividef(1.f, g_sum[b]);
            out[b * DDIM + tid] = g_acc[b * DDIM + tid] * inv;
        }
        __syncthreads();                    // reads done before reset
        #pragma unroll 4
        for (int b = 0; b < BATCH; b++) g_acc[b * DDIM + tid] = 0.f;
        if (tid < BATCH) g_sum[tid] = 0.f;
        if (tid == 0) { g_unit = 0u; g_done = 0u; }
    }
}

extern "C" void kernel_launch(void* const* d_in, const int* in_sizes, int n_in,
                              void* d_out, int out_size)
{
    // Map inputs by element count:
    //   memory: B*S*D = 67108864, aspect: B*D = 16384, W: 2*D = 512, b: 1
    const float *aspect = nullptr, *memory = nullptr, *W = nullptr, *bias = nullptr;
    for (int i = 0; i < n_in; i++) {
        const long n = (long)in_sizes[i];
        const float* p = (const float*)d_in[i];
        if      (n == (long)BATCH * SDIM * DDIM) memory = p;
        else if (n == (long)BATCH * DDIM)        aspect = p;
        else if (n == 2 * DDIM)                  W      = p;
        else if (n == 1)                         bias   = p;
    }

    att_persist<<<GRID, 256>>>(memory, aspect, W, bias, (float*)d_out);
}

// round 14
// speedup vs baseline: 2.0868x; 2.0868x over previous
#include <cuda_runtime.h>
#include <cuda_bf16.h>

// Problem dims
#define BATCH  64
#define SDIM   4096
#define DDIM   256
#define SCHUNK 512
#define NCHUNK (SDIM / SCHUNK)          // 8
#define NBLK   (BATCH * NCHUNK)         // 512 CTAs, occ 4, single wave

// Scratch for cross-CTA partials (no allocation allowed -> device globals)
__device__ float g_acc[NBLK * DDIM];    // 512 KB
__device__ float g_sum[NBLK];
__device__ int   g_cnt[BATCH];          // zero-init; re-armed by finalizer each run

__device__ __forceinline__ float warp_sum(float v) {
    #pragma unroll
    for (int o = 16; o; o >>= 1) v += __shfl_xor_sync(0xffffffffu, v, o);
    return v;
}

// exp(tanh(x)) via tanh(x) = 1 - 2/(e^{2x}+1); saturates correctly at +-1.
// Validated at rel_err ~1.0e-6 across R9-R12.
__device__ __forceinline__ float exp_tanh(float x) {
    const float t  = __expf(2.f * x);
    const float th = 1.f - __fdividef(2.f, t + 1.f);
    return __expf(th);
}

__device__ __forceinline__ float dot8(const float4& m0, const float4& m1,
                                      const float4& w0, const float4& w1) {
    return m0.x * w0.x + m0.y * w0.y + m0.z * w0.z + m0.w * w0.w
         + m1.x * w1.x + m1.y * w1.y + m1.z * w1.z + m1.w * w1.w;
}

// ---------------------------------------------------------------------------
// Single pass over memory (268 MB read exactly once):
//   gi = tanh(m·Wm + c_b) in [-1,1] => exp never overflows => softmax needs
//   no running max; accumulate exp(gi)*m and exp(gi) in one sweep.
// R12 structure (best measured) with the launch serial section removed:
//   - first streaming loads issue BEFORE anything else (DRAM ramps at once)
//   - cb computed redundantly per-warp from L2-broadcast data: NO
//     __syncthreads anywhere before the hot loop
//   - last 2 iterations peeled -> guard-free steady-state prefetch
// R13 lesson honored: zero CTA-wide sync on the hot path.
// Last CTA per batch finalizes (threadfence-reduction pattern).
// ---------------------------------------------------------------------------
__global__ __launch_bounds__(256, 4)
void att_fused(const float* __restrict__ memory,
               const float* __restrict__ aspect,
               const float* __restrict__ W,
               const float* __restrict__ bias,
               float* __restrict__ out)
{
    __shared__ float slab[8][DDIM];      // per-warp partial vectors (8 KB)
    __shared__ float wsum[8];
    __shared__ int   s_old;

    const int tid  = threadIdx.x;
    const int lane = tid & 31;
    const int warp = tid >> 5;
    const int blk  = blockIdx.x;
    const int b    = blk >> 3;           // / NCHUNK
    const int chnk = blk & (NCHUNK - 1);

    const float4* base = reinterpret_cast<const float4*>(
        memory + ((long)b * SDIM + (long)chnk * SCHUNK) * DDIM);
    // row r occupies float4s [r*64, r*64+64); this warp does r = warp + 8*i
    const float4* p = base + (long)warp * 64;
    const long rstep = 8 * 64;           // 8 rows ahead per i

    // ---- FIRST: get the memory stream going (rows i=0,1 in flight) ----
    float4 c00 = __ldcs(p + lane),             c01 = __ldcs(p + 32 + lane);
    float4 c10 = __ldcs(p + rstep + lane),     c11 = __ldcs(p + rstep + 32 + lane);

    // ---- cb per-warp, sync-free (aspect/W are L2-broadcast, 1.3 KB) ----
    float cb;
    {
        float v = 0.f;
        #pragma unroll
        for (int k = 0; k < 8; k++)
            v += aspect[b * DDIM + lane + 32 * k] * W[DDIM + lane + 32 * k];
        cb = warp_sum(v) + bias[0];
    }

    // ---- Wm slice in registers: lane covers d = 4*lane.. and 128+4*lane.. ----
    const float4 wm0 = *reinterpret_cast<const float4*>(W + 4 * lane);
    const float4 wm1 = *reinterpret_cast<const float4*>(W + 128 + 4 * lane);

    float4 a0 = make_float4(0.f, 0.f, 0.f, 0.f);
    float4 a1 = make_float4(0.f, 0.f, 0.f, 0.f);
    float  sw = 0.f;

    // steady state: 31 iterations with unconditional 2-row prefetch
    #pragma unroll 2
    for (int i = 0; i < 62; i += 2) {
        const float4* q = p + (long)(i + 2) * rstep;
        const float4 n00 = __ldcs(q + lane);          const float4 n01 = __ldcs(q + 32 + lane);
        const float4 n10 = __ldcs(q + rstep + lane);  const float4 n11 = __ldcs(q + rstep + 32 + lane);

        float d0 = warp_sum(dot8(c00, c01, wm0, wm1));
        float d1 = warp_sum(dot8(c10, c11, wm0, wm1));
        const float w0 = exp_tanh(d0 + cb);
        const float w1 = exp_tanh(d1 + cb);

        a0.x += w0 * c00.x + w1 * c10.x;  a0.y += w0 * c00.y + w1 * c10.y;
        a0.z += w0 * c00.z + w1 * c10.z;  a0.w += w0 * c00.w + w1 * c10.w;
        a1.x += w0 * c01.x + w1 * c11.x;  a1.y += w0 * c01.y + w1 * c11.y;
        a1.z += w0 * c01.z + w1 * c11.z;  a1.w += w0 * c01.w + w1 * c11.w;
        sw   += w0 + w1;                  // uniform across lanes post-butterfly

        c00 = n00; c01 = n01; c10 = n10; c11 = n11;
    }
    // peeled final pair (rows 62,63 already resident in c**)
    {
        float d0 = warp_sum(dot8(c00, c01, wm0, wm1));
        float d1 = warp_sum(dot8(c10, c11, wm0, wm1));
        const float w0 = exp_tanh(d0 + cb);
        const float w1 = exp_tanh(d1 + cb);
        a0.x += w0 * c00.x + w1 * c10.x;  a0.y += w0 * c00.y + w1 * c10.y;
        a0.z += w0 * c00.z + w1 * c10.z;  a0.w += w0 * c00.w + w1 * c10.w;
        a1.x += w0 * c01.x + w1 * c11.x;  a1.y += w0 * c01.y + w1 * c11.y;
        a1.z += w0 * c01.z + w1 * c11.z;  a1.w += w0 * c01.w + w1 * c11.w;
        sw   += w0 + w1;
    }

    // ---- deterministic 8-warp combine via slab ----
    float* my = &slab[warp][0];
    my[4 * lane + 0] = a0.x;  my[4 * lane + 1] = a0.y;
    my[4 * lane + 2] = a0.z;  my[4 * lane + 3] = a0.w;
    my[128 + 4 * lane + 0] = a1.x;  my[128 + 4 * lane + 1] = a1.y;
    my[128 + 4 * lane + 2] = a1.z;  my[128 + 4 * lane + 3] = a1.w;
    if (lane == 0) wsum[warp] = sw;
    __syncthreads();

    {
        float t = 0.f;
        #pragma unroll
        for (int w = 0; w < 8; w++) t += slab[w][tid];
        g_acc[blk * DDIM + tid] = t;
        if (tid == 0) {
            float s = 0.f;
            #pragma unroll
            for (int w = 0; w < 8; w++) s += wsum[w];
            g_sum[blk] = s;
        }
    }
    __syncthreads();

    // ---- last-CTA-per-batch finalize (threadfence-reduction pattern) ----
    if (tid == 0) {
        __threadfence();
        s_old = atomicAdd(&g_cnt[b], 1);
    }
    __syncthreads();
    if (s_old == NCHUNK - 1) {
        __threadfence();                  // acquire siblings' partials
        float acc = 0.f, s = 0.f;
        #pragma unroll
        for (int c = 0; c < NCHUNK; c++) {
            acc += g_acc[(b * NCHUNK + c) * DDIM + tid];
            s   += g_sum[b * NCHUNK + c];
        }
        out[b * DDIM + tid] = acc * __fdividef(1.f, s);
        __syncthreads();
        if (tid == 0) g_cnt[b] = 0;       // re-arm for next graph replay
    }
}

extern "C" void kernel_launch(void* const* d_in, const int* in_sizes, int n_in,
                              void* d_out, int out_size)
{
    // Map inputs by element count:
    //   memory: B*S*D = 67108864, aspect: B*D = 16384, W: 2*D = 512, b: 1
    const float *aspect = nullptr, *memory = nullptr, *W = nullptr, *bias = nullptr;
    for (int i = 0; i < n_in; i++) {
        const long n = (long)in_sizes[i];
        const float* p = (const float*)d_in[i];
        if      (n == (long)BATCH * SDIM * DDIM) memory = p;
        else if (n == (long)BATCH * DDIM)        aspect = p;
        else if (n == 2 * DDIM)                  W      = p;
        else if (n == 1)                         bias   = p;
    }

    att_fused<<<NBLK, 256>>>(memory, aspect, W, bias, (float*)d_out);
}